// round 7
// baseline (speedup 1.0000x reference)
#include <cuda_runtime.h>
#include <cstdint>

// Inverse 2D Haar wavelet (synthesis), fixed shapes:
//   in : (B=32, C4=256, H=64, W=64) f32   (C4 = C*4: cA,cH,cV,cD per channel)
//   out: (B=32, C=64, 128, 128) f32
//
// Thread = 4 input cols of one row: 4x LDG.128 (one per subband),
// 2x STG.256 (v8.b32) to output rows 2h / 2h+1, all fully coalesced.
//
// L2 policy (address-stable partial pinning):
//   input channels bc < PIN_CHANNELS (80MB, fits in 126MB L2): evict_last
//     -> survives across graph replays, reads become L2 hits
//   remaining reads + all stores: evict_first -> stream through without
//     churning the pinned set. (Uniform evict_last on a 134MB stream
//     cyclically thrashes a 126MB L2 — the pinned subset must FIT.)

#define IWT_H 64
#define IWT_W 64
#define PLANE_IN  (IWT_H * IWT_W)          // 4096
#define PLANE_OUT (4 * IWT_H * IWT_W)      // 16384
#define PIN_CHANNELS 1280                  // 1280 * 64KB = 80MB pinned input

__device__ __forceinline__ float4 ldg4_pol(const float* p, uint64_t pol) {
    float4 v;
    asm volatile("ld.global.L2::cache_hint.v4.f32 {%0,%1,%2,%3}, [%4], %5;"
                 : "=f"(v.x), "=f"(v.y), "=f"(v.z), "=f"(v.w)
                 : "l"(p), "l"(pol));
    return v;
}

__device__ __forceinline__ void stg8_pol(float* p, const float* r, uint64_t pol) {
    asm volatile("st.global.L2::cache_hint.v8.b32 [%0], {%1,%2,%3,%4,%5,%6,%7,%8}, %9;"
                 :: "l"(p),
                    "r"(__float_as_uint(r[0])), "r"(__float_as_uint(r[1])),
                    "r"(__float_as_uint(r[2])), "r"(__float_as_uint(r[3])),
                    "r"(__float_as_uint(r[4])), "r"(__float_as_uint(r[5])),
                    "r"(__float_as_uint(r[6])), "r"(__float_as_uint(r[7])),
                    "l"(pol)
                 : "memory");
}

__global__ void __launch_bounds__(256, 8) iwt_kernel(
    const float* __restrict__ x, float* __restrict__ out)
{
    uint64_t pol_keep, pol_stream;
    asm volatile("createpolicy.fractional.L2::evict_last.b64 %0, 1.0;"
                 : "=l"(pol_keep));
    asm volatile("createpolicy.fractional.L2::evict_first.b64 %0, 1.0;"
                 : "=l"(pol_stream));

    int t = blockIdx.x * blockDim.x + threadIdx.x;
    int i  = t & 15;           // 16 threads per row, 4 cols each
    int h  = (t >> 4) & 63;
    int bc = t >> 10;          // 0 .. 2047

    uint64_t lpol = (bc < PIN_CHANNELS) ? pol_keep : pol_stream;

    const float* base = x + (size_t)bc * 4 * PLANE_IN + h * IWT_W + 4 * i;
    float4 a  = ldg4_pol(base,                lpol);
    float4 hh = ldg4_pol(base + PLANE_IN,     lpol);
    float4 v  = ldg4_pol(base + 2 * PLANE_IN, lpol);
    float4 d  = ldg4_pol(base + 3 * PLANE_IN, lpol);

    float r0[8], r1[8];
    {
        float ai = a.x, hi = hh.x, vi = v.x, di = d.x;
        r0[0] = (ai + hi + vi + di) * 0.5f;
        r0[1] = (ai + hi - vi - di) * 0.5f;
        r1[0] = (ai - hi + vi - di) * 0.5f;
        r1[1] = (ai - hi - vi + di) * 0.5f;
    }
    {
        float ai = a.y, hi = hh.y, vi = v.y, di = d.y;
        r0[2] = (ai + hi + vi + di) * 0.5f;
        r0[3] = (ai + hi - vi - di) * 0.5f;
        r1[2] = (ai - hi + vi - di) * 0.5f;
        r1[3] = (ai - hi - vi + di) * 0.5f;
    }
    {
        float ai = a.z, hi = hh.z, vi = v.z, di = d.z;
        r0[4] = (ai + hi + vi + di) * 0.5f;
        r0[5] = (ai + hi - vi - di) * 0.5f;
        r1[4] = (ai - hi + vi - di) * 0.5f;
        r1[5] = (ai - hi - vi + di) * 0.5f;
    }
    {
        float ai = a.w, hi = hh.w, vi = v.w, di = d.w;
        r0[6] = (ai + hi + vi + di) * 0.5f;
        r0[7] = (ai + hi - vi - di) * 0.5f;
        r1[6] = (ai - hi + vi - di) * 0.5f;
        r1[7] = (ai - hi - vi + di) * 0.5f;
    }

    float* o = out + (size_t)bc * PLANE_OUT + (2 * h) * (2 * IWT_W) + 8 * i;
    stg8_pol(o,               r0, pol_stream);   // row 2h
    stg8_pol(o + 2 * IWT_W,   r1, pol_stream);   // row 2h+1
}

extern "C" void kernel_launch(void* const* d_in, const int* in_sizes, int n_in,
                              void* d_out, int out_size) {
    const float* x = (const float*)d_in[0];
    float* out = (float*)d_out;

    int total = in_sizes[0];            // 33,554,432 elems
    int threads_total = total / 16;     // 16 input elems per thread

    int threads = 256;
    int blocks = threads_total / threads;   // 8192
    iwt_kernel<<<blocks, threads>>>(x, out);
}

// round 8
// speedup vs baseline: 1.0368x; 1.0368x over previous
#include <cuda_runtime.h>
#include <cstdint>

// Inverse 2D Haar wavelet (synthesis), fixed shapes:
//   in : (B=32, C4=256, H=64, W=64) f32   (C4 = C*4: cA,cH,cV,cD per channel)
//   out: (B=32, C=64, 128, 128) f32
//
// Warp-per-input-row mapping (best known):
//   lane i loads input cols [2i,2i+2) per subband (float2, 256B/warp/subband)
//   lane i stores output cols [4i,4i+4) of rows 2h, 2h+1 (float4, 512B/warp/STG)
//
// Loads use __ldcg (L2-only, skip L1 fill): input is single-use, so the L1
// fill is pure overhead; frees L1tex bandwidth for the store wavefronts.
// L2 persistence hints removed — evict_last needs the persisting carveout
// (cudaDeviceSetLimit), which the harness forbids; they were no-ops.

#define IWT_H 64
#define IWT_W 64
#define PLANE_IN  (IWT_H * IWT_W)          // 4096
#define PLANE_OUT (4 * IWT_H * IWT_W)      // 16384

__global__ void __launch_bounds__(512) iwt_kernel(
    const float* __restrict__ x, float* __restrict__ out)
{
    int t = blockIdx.x * blockDim.x + threadIdx.x;
    int lane = t & 31;
    int w = t >> 5;          // warp index = (bc, h)
    int h = w & 63;
    int bc = w >> 6;         // 0 .. B*C-1 (2048)

    const float2* base = (const float2*)(x + (size_t)bc * 4 * PLANE_IN + h * IWT_W + 2 * lane);
    float2 a  = __ldcg(base);
    float2 hh = __ldcg(base + PLANE_IN / 2);
    float2 v  = __ldcg(base + 2 * PLANE_IN / 2);
    float2 d  = __ldcg(base + 3 * PLANE_IN / 2);

    float4 r0, r1;
    {
        float ai = a.x, hi = hh.x, vi = v.x, di = d.x;
        r0.x = (ai + hi + vi + di) * 0.5f;
        r0.y = (ai + hi - vi - di) * 0.5f;
        r1.x = (ai - hi + vi - di) * 0.5f;
        r1.y = (ai - hi - vi + di) * 0.5f;
    }
    {
        float ai = a.y, hi = hh.y, vi = v.y, di = d.y;
        r0.z = (ai + hi + vi + di) * 0.5f;
        r0.w = (ai + hi - vi - di) * 0.5f;
        r1.z = (ai - hi + vi - di) * 0.5f;
        r1.w = (ai - hi - vi + di) * 0.5f;
    }

    float* o = out + (size_t)bc * PLANE_OUT + (2 * h) * (2 * IWT_W) + 4 * lane;
    *(float4*)(o)              = r0;   // row 2h
    *(float4*)(o + 2 * IWT_W)  = r1;   // row 2h+1
}

extern "C" void kernel_launch(void* const* d_in, const int* in_sizes, int n_in,
                              void* d_out, int out_size) {
    const float* x = (const float*)d_in[0];
    float* out = (float*)d_out;

    int total = in_sizes[0];            // 33,554,432 elems
    int threads_total = total / 8;      // 8 elems per thread

    int threads = 512;
    int blocks = threads_total / threads;   // 8192
    iwt_kernel<<<blocks, threads>>>(x, out);
}